// round 1
// baseline (speedup 1.0000x reference)
#include <cuda_runtime.h>
#include <math.h>

#define B_  2
#define L_  1024
#define H_  16
#define D_  64
#define HID_ 1024
#define N3_ 3072
#define HD_ 1024   // H*D
#define M_  2048   // B*L

// ---------------- scratch (device globals; no allocations) ----------------
__device__ float g_q[B_ * H_ * L_ * D_];   // (B,H,L,D)
__device__ float g_k[B_ * H_ * L_ * D_];
__device__ float g_v[B_ * H_ * L_ * D_];
__device__ float g_s[B_ * H_ * L_ * L_];   // scores / weights, 128 MB
__device__ float g_o[B_ * L_ * HD_];       // attention output (B,L,H*D)

// ---------------- kernel 1: qkv = x @ w_qkv, epilogue scatter to q/k/v ----------------
__global__ void k_qkv(const float* __restrict__ X, const float* __restrict__ W) {
    __shared__ float As[64][17];
    __shared__ float Bs[16][64];
    int tx = threadIdx.x, ty = threadIdx.y;
    int tid = ty * 16 + tx;
    int m0 = blockIdx.y * 64, n0 = blockIdx.x * 64;
    float acc[4][4] = {};

    for (int k0 = 0; k0 < HID_; k0 += 16) {
        {   // A: 64 rows x 16 cols
            int row = tid >> 2, q = (tid & 3) * 4;
            float4 v = *reinterpret_cast<const float4*>(X + (m0 + row) * HID_ + k0 + q);
            As[row][q + 0] = v.x; As[row][q + 1] = v.y;
            As[row][q + 2] = v.z; As[row][q + 3] = v.w;
        }
        {   // B: 16 rows x 64 cols
            int row = tid >> 4, c4 = (tid & 15) * 4;
            float4 v = *reinterpret_cast<const float4*>(W + (k0 + row) * N3_ + n0 + c4);
            *reinterpret_cast<float4*>(&Bs[row][c4]) = v;
        }
        __syncthreads();
        #pragma unroll
        for (int k = 0; k < 16; k++) {
            float a[4], b[4];
            #pragma unroll
            for (int r = 0; r < 4; r++) a[r] = As[ty + 16 * r][k];
            #pragma unroll
            for (int c = 0; c < 4; c++) b[c] = Bs[k][tx + 16 * c];
            #pragma unroll
            for (int r = 0; r < 4; r++)
                #pragma unroll
                for (int c = 0; c < 4; c++) acc[r][c] += a[r] * b[c];
        }
        __syncthreads();
    }
    #pragma unroll
    for (int r = 0; r < 4; r++) {
        int m = m0 + ty + 16 * r;
        int b = m >> 10, l = m & 1023;
        #pragma unroll
        for (int c = 0; c < 4; c++) {
            int n = n0 + tx + 16 * c;
            int s = n >> 10, rem = n & 1023;
            int h = rem >> 6, d = rem & 63;
            float* dst = (s == 0) ? g_q : (s == 1) ? g_k : g_v;
            dst[((b * H_ + h) * L_ + l) * D_ + d] = acc[r][c];
        }
    }
}

// ---------------- kernel 2: RoPE in place on q,k ----------------
__global__ void k_rope() {
    int t = blockIdx.x * 256 + threadIdx.x;     // B*H*L*32 threads
    int bh = t >> 15;
    int rem = t & 32767;
    int l = rem >> 5;
    int j = rem & 31;
    float invf = expf(-(float)j * (logf(10000.0f) / 32.0f));
    float ang = (float)l * invf;
    float cs = cosf(ang), sn = sinf(ang);
    int base = (bh << 16) + (l << 6) + j;
    float q1 = g_q[base], q2 = g_q[base + 32];
    g_q[base]      = q1 * cs - q2 * sn;
    g_q[base + 32] = q2 * cs + q1 * sn;
    float k1 = g_k[base], k2 = g_k[base + 32];
    g_k[base]      = k1 * cs - k2 * sn;
    g_k[base + 32] = k2 * cs + k1 * sn;
}

// ---------------- kernel 3: scores = q k^T * scale (lower-tri tiles only) ----------------
__global__ void k_scores() {
    int jt = blockIdx.x, it = blockIdx.y, bh = blockIdx.z;
    if (jt > it) return;
    __shared__ float Qs[64][65];
    __shared__ float Ks[64][65];
    int tx = threadIdx.x, ty = threadIdx.y;
    int tid = ty * 16 + tx;
    int i0 = it * 64, j0 = jt * 64;
    const float* qb = g_q + (bh * L_ + i0) * D_;
    const float* kb = g_k + (bh * L_ + j0) * D_;
    #pragma unroll
    for (int rr = 0; rr < 4; rr++) {
        int row = (tid >> 4) + rr * 16;
        int c4 = (tid & 15) * 4;
        float4 vq = *reinterpret_cast<const float4*>(qb + row * D_ + c4);
        Qs[row][c4] = vq.x; Qs[row][c4 + 1] = vq.y; Qs[row][c4 + 2] = vq.z; Qs[row][c4 + 3] = vq.w;
        float4 vk = *reinterpret_cast<const float4*>(kb + row * D_ + c4);
        Ks[row][c4] = vk.x; Ks[row][c4 + 1] = vk.y; Ks[row][c4 + 2] = vk.z; Ks[row][c4 + 3] = vk.w;
    }
    __syncthreads();
    float acc[4][4] = {};
    #pragma unroll
    for (int d = 0; d < 64; d++) {
        float a[4], b[4];
        #pragma unroll
        for (int r = 0; r < 4; r++) a[r] = Qs[ty + 16 * r][d];
        #pragma unroll
        for (int c = 0; c < 4; c++) b[c] = Ks[tx + 16 * c][d];
        #pragma unroll
        for (int r = 0; r < 4; r++)
            #pragma unroll
            for (int c = 0; c < 4; c++) acc[r][c] += a[r] * b[c];
    }
    bool diag = (it == jt);
    #pragma unroll
    for (int r = 0; r < 4; r++) {
        int i = i0 + ty + 16 * r;
        #pragma unroll
        for (int c = 0; c < 4; c++) {
            int j = j0 + tx + 16 * c;
            float v = acc[r][c] * 0.125f;
            if (diag && j > i) v = 0.0f;           // stays 0 through softmax; PV needs no mask
            g_s[(bh * L_ + i) * L_ + j] = v;
        }
    }
}

// ---------------- kernel 4: kerple bias + DAPE MLP, in place (j<=i only) ----------------
__global__ void k_dape(const float* __restrict__ log_p, const float* __restrict__ log_a,
                       const float* __restrict__ w1, const float* __restrict__ b1,
                       const float* __restrict__ w2, const float* __restrict__ b2) {
    __shared__ float w1s[1024];
    __shared__ float w2s[512];
    __shared__ float b1s[32], b2s[16], ps[16], as_[16];
    int tx = threadIdx.x;
    for (int t = tx; t < 1024; t += 256) w1s[t] = w1[t];
    for (int t = tx; t < 512; t += 256) w2s[t] = w2[t];
    if (tx < 32) b1s[tx] = b1[tx];
    if (tx < 16) {
        b2s[tx] = b2[tx];
        ps[tx]  = log1pf(expf(log_p[tx]));
        as_[tx] = log1pf(expf(log_a[tx]));
    }
    __syncthreads();

    int i = blockIdx.y;
    int bb = blockIdx.z;
    int j = blockIdx.x * 256 + tx;
    if (j > i) return;
    float dist = (float)(i - j);
    int off = bb * (H_ * L_ * L_) + i * L_ + j;

    float c[32];
    #pragma unroll
    for (int h = 0; h < 16; h++) c[h] = g_s[off + h * (L_ * L_)];
    #pragma unroll
    for (int h = 0; h < 16; h++) c[16 + h] = -ps[h] * log1pf(as_[h] * dist);

    float ref[16];
    #pragma unroll
    for (int h = 0; h < 16; h++) ref[h] = b2s[h];

    #pragma unroll 4
    for (int u = 0; u < 32; u++) {
        float acc = b1s[u];
        #pragma unroll
        for (int kk = 0; kk < 32; kk++) acc += c[kk] * w1s[kk * 32 + u];
        float g = 0.5f * acc * (1.0f + erff(acc * 0.70710678118f));
        #pragma unroll
        for (int h = 0; h < 16; h++) ref[h] += g * w2s[u * 16 + h];
    }
    #pragma unroll
    for (int h = 0; h < 16; h++)
        g_s[off + h * (L_ * L_)] = c[h] + c[16 + h] + ref[h];
}

// ---------------- kernel 5: causal softmax per row ----------------
__global__ void k_softmax() {
    int row = blockIdx.x;           // bh*L + i
    int i = row & 1023;
    int n = i + 1;
    float* S = g_s + (size_t)row * L_;
    __shared__ float buf[1024];
    __shared__ float redm[4], reds[4];
    int tx = threadIdx.x;

    float m = -1e30f;
    for (int j = tx; j < n; j += 128) { float v = S[j]; buf[j] = v; m = fmaxf(m, v); }
    #pragma unroll
    for (int o = 16; o; o >>= 1) m = fmaxf(m, __shfl_xor_sync(0xffffffffu, m, o));
    if ((tx & 31) == 0) redm[tx >> 5] = m;
    __syncthreads();
    m = fmaxf(fmaxf(redm[0], redm[1]), fmaxf(redm[2], redm[3]));

    float sum = 0.0f;
    for (int j = tx; j < n; j += 128) { float e = expf(buf[j] - m); buf[j] = e; sum += e; }
    #pragma unroll
    for (int o = 16; o; o >>= 1) sum += __shfl_xor_sync(0xffffffffu, sum, o);
    if ((tx & 31) == 0) reds[tx >> 5] = sum;
    __syncthreads();
    sum = reds[0] + reds[1] + reds[2] + reds[3];
    float inv = 1.0f / sum;
    for (int j = tx; j < n; j += 128) S[j] = buf[j] * inv;
}

// ---------------- kernel 6: out = weights @ v (lower-tri j loop) ----------------
__global__ void k_pv() {
    int it = blockIdx.x, bh = blockIdx.y;
    int tx = threadIdx.x, ty = threadIdx.y;
    int tid = ty * 16 + tx;
    int i0 = it * 64;
    __shared__ float Ws[64][65];
    __shared__ float Vs[64][65];
    float acc[4][4] = {};

    for (int jt = 0; jt <= it; jt++) {
        int j0 = jt * 64;
        const float* wb = g_s + (size_t)(bh * L_ + i0) * L_ + j0;
        const float* vb = g_v + (bh * L_ + j0) * D_;
        #pragma unroll
        for (int rr = 0; rr < 4; rr++) {
            int row = (tid >> 4) + rr * 16;
            int c4 = (tid & 15) * 4;
            float4 vw = *reinterpret_cast<const float4*>(wb + (size_t)row * L_ + c4);
            Ws[row][c4] = vw.x; Ws[row][c4 + 1] = vw.y; Ws[row][c4 + 2] = vw.z; Ws[row][c4 + 3] = vw.w;
            float4 vv = *reinterpret_cast<const float4*>(vb + row * D_ + c4);
            Vs[row][c4] = vv.x; Vs[row][c4 + 1] = vv.y; Vs[row][c4 + 2] = vv.z; Vs[row][c4 + 3] = vv.w;
        }
        __syncthreads();
        #pragma unroll
        for (int jj = 0; jj < 64; jj++) {
            float a[4], b[4];
            #pragma unroll
            for (int r = 0; r < 4; r++) a[r] = Ws[ty + 16 * r][jj];
            #pragma unroll
            for (int c = 0; c < 4; c++) b[c] = Vs[jj][tx + 16 * c];
            #pragma unroll
            for (int r = 0; r < 4; r++)
                #pragma unroll
                for (int c = 0; c < 4; c++) acc[r][c] += a[r] * b[c];
        }
        __syncthreads();
    }
    int b = bh >> 4, h = bh & 15;
    #pragma unroll
    for (int r = 0; r < 4; r++) {
        int i = i0 + ty + 16 * r;
        #pragma unroll
        for (int c = 0; c < 4; c++) {
            int d = tx + 16 * c;
            g_o[(b * L_ + i) * HD_ + h * D_ + d] = acc[r][c];
        }
    }
}

// ---------------- kernel 7: y = g_o @ w_o -> d_out ----------------
__global__ void k_out(const float* __restrict__ W, float* __restrict__ Y) {
    __shared__ float As[64][17];
    __shared__ float Bs[16][64];
    int tx = threadIdx.x, ty = threadIdx.y;
    int tid = ty * 16 + tx;
    int m0 = blockIdx.y * 64, n0 = blockIdx.x * 64;
    float acc[4][4] = {};

    for (int k0 = 0; k0 < HD_; k0 += 16) {
        {
            int row = tid >> 2, q = (tid & 3) * 4;
            float4 v = *reinterpret_cast<const float4*>(g_o + (m0 + row) * HD_ + k0 + q);
            As[row][q + 0] = v.x; As[row][q + 1] = v.y;
            As[row][q + 2] = v.z; As[row][q + 3] = v.w;
        }
        {
            int row = tid >> 4, c4 = (tid & 15) * 4;
            float4 v = *reinterpret_cast<const float4*>(W + (k0 + row) * HID_ + n0 + c4);
            *reinterpret_cast<float4*>(&Bs[row][c4]) = v;
        }
        __syncthreads();
        #pragma unroll
        for (int k = 0; k < 16; k++) {
            float a[4], b[4];
            #pragma unroll
            for (int r = 0; r < 4; r++) a[r] = As[ty + 16 * r][k];
            #pragma unroll
            for (int c = 0; c < 4; c++) b[c] = Bs[k][tx + 16 * c];
            #pragma unroll
            for (int r = 0; r < 4; r++)
                #pragma unroll
                for (int c = 0; c < 4; c++) acc[r][c] += a[r] * b[c];
        }
        __syncthreads();
    }
    #pragma unroll
    for (int r = 0; r < 4; r++) {
        int m = m0 + ty + 16 * r;
        #pragma unroll
        for (int c = 0; c < 4; c++) {
            int n = n0 + tx + 16 * c;
            Y[m * HID_ + n] = acc[r][c];
        }
    }
}

// ---------------- launch ----------------
extern "C" void kernel_launch(void* const* d_in, const int* in_sizes, int n_in,
                              void* d_out, int out_size) {
    const float* x     = (const float*)d_in[0];
    const float* w_qkv = (const float*)d_in[1];
    const float* w_o   = (const float*)d_in[2];
    const float* log_p = (const float*)d_in[3];
    const float* log_a = (const float*)d_in[4];
    const float* w1    = (const float*)d_in[5];
    const float* b1    = (const float*)d_in[6];
    const float* w2    = (const float*)d_in[7];
    const float* b2    = (const float*)d_in[8];
    float* y = (float*)d_out;

    dim3 blk16(16, 16);

    // 1. QKV projection
    k_qkv<<<dim3(N3_ / 64, M_ / 64), blk16>>>(x, w_qkv);
    // 2. RoPE
    k_rope<<<(B_ * H_ * L_ * 32) / 256, 256>>>();
    // 3. scores (lower-tri tiles)
    k_scores<<<dim3(16, 16, B_ * H_), blk16>>>();
    // 4. kerple + DAPE MLP
    k_dape<<<dim3(4, L_, B_), 256>>>(log_p, log_a, w1, b1, w2, b2);
    // 5. causal softmax
    k_softmax<<<B_ * H_ * L_, 128>>>();
    // 6. PV
    k_pv<<<dim3(16, B_ * H_), blk16>>>();
    // 7. output projection
    k_out<<<dim3(HID_ / 64, M_ / 64), blk16>>>(w_o, y);
}

// round 2
// speedup vs baseline: 1.7378x; 1.7378x over previous
#include <cuda_runtime.h>
#include <math.h>

#define B_  2
#define L_  1024
#define H_  16
#define D_  64
#define HID_ 1024
#define N3_ 3072
#define HD_ 1024   // H*D
#define M_  2048   // B*L

// ---------------- scratch (device globals; no allocations) ----------------
__device__ float g_q[B_ * H_ * L_ * D_];   // (B,H,L,D)
__device__ float g_k[B_ * H_ * L_ * D_];
__device__ float g_v[B_ * H_ * L_ * D_];
__device__ float g_s[B_ * H_ * L_ * L_];   // scores / weights, 128 MB
__device__ float g_o[B_ * L_ * HD_];       // attention output (B,L,H*D)

// ---------------- tf32 helpers ----------------
__device__ __forceinline__ unsigned f2tf(float x) {
    unsigned r;
    asm("cvt.rna.tf32.f32 %0, %1;" : "=r"(r) : "f"(x));
    return r;
}

__device__ __forceinline__ void mma_tf32(float& d0, float& d1, float& d2, float& d3,
                                         unsigned a0, unsigned a1, unsigned a2, unsigned a3,
                                         unsigned b0, unsigned b1) {
    asm volatile(
        "mma.sync.aligned.m16n8k8.row.col.f32.tf32.tf32.f32 "
        "{%0,%1,%2,%3}, {%4,%5,%6,%7}, {%8,%9}, {%0,%1,%2,%3};"
        : "+f"(d0), "+f"(d1), "+f"(d2), "+f"(d3)
        : "r"(a0), "r"(a1), "r"(a2), "r"(a3), "r"(b0), "r"(b1));
}

// ---------------- generic tf32 mma GEMM: C(M x N) = A(M x 1024) @ B(1024 x N) ----------------
// BM=128, BN=128, BK=32, 256 threads (8 warps: 4 over M, 2 over N; warp tile 32x64)
// MODE 0: plain store, C row-major with ld = NLD
// MODE 1: qkv scatter epilogue into g_q/g_k/g_v
#define SA_ 36
#define SB_ 136

template<int NLD, int MODE>
__global__ void __launch_bounds__(256)
k_gemm_mma(const float* __restrict__ A, const float* __restrict__ Bm, float* __restrict__ C) {
    __shared__ unsigned sA[128 * SA_];
    __shared__ unsigned sB[32 * SB_];

    int tid = threadIdx.x;
    int lane = tid & 31, wid = tid >> 5;
    int g = lane >> 2, t4 = lane & 3;
    int wm = wid & 3, wn = wid >> 2;          // warp tile origin: (wm*32, wn*64)
    int m0 = blockIdx.y * 128, n0 = blockIdx.x * 128;

    float acc[2][8][4];
    #pragma unroll
    for (int mt = 0; mt < 2; mt++)
        #pragma unroll
        for (int nt = 0; nt < 8; nt++)
            #pragma unroll
            for (int c = 0; c < 4; c++) acc[mt][nt][c] = 0.0f;

    for (int k0 = 0; k0 < HID_; k0 += 32) {
        // load A tile 128x32 (4 float4 per thread)
        #pragma unroll
        for (int it = 0; it < 4; it++) {
            int row = it * 32 + (tid >> 3);
            int col = (tid & 7) * 4;
            float4 v = *reinterpret_cast<const float4*>(A + (size_t)(m0 + row) * HID_ + k0 + col);
            sA[row * SA_ + col + 0] = f2tf(v.x);
            sA[row * SA_ + col + 1] = f2tf(v.y);
            sA[row * SA_ + col + 2] = f2tf(v.z);
            sA[row * SA_ + col + 3] = f2tf(v.w);
        }
        // load B tile 32x128
        #pragma unroll
        for (int it = 0; it < 4; it++) {
            int row = it * 8 + (tid >> 5);
            int col = (tid & 31) * 4;
            float4 v = *reinterpret_cast<const float4*>(Bm + (size_t)(k0 + row) * NLD + n0 + col);
            sB[row * SB_ + col + 0] = f2tf(v.x);
            sB[row * SB_ + col + 1] = f2tf(v.y);
            sB[row * SB_ + col + 2] = f2tf(v.z);
            sB[row * SB_ + col + 3] = f2tf(v.w);
        }
        __syncthreads();

        #pragma unroll
        for (int ks = 0; ks < 4; ks++) {
            int kk = ks * 8;
            unsigned af[2][4];
            #pragma unroll
            for (int mt = 0; mt < 2; mt++) {
                int r = wm * 32 + mt * 16 + g;
                af[mt][0] = sA[r * SA_ + kk + t4];
                af[mt][1] = sA[(r + 8) * SA_ + kk + t4];
                af[mt][2] = sA[r * SA_ + kk + t4 + 4];
                af[mt][3] = sA[(r + 8) * SA_ + kk + t4 + 4];
            }
            unsigned bf[8][2];
            #pragma unroll
            for (int nt = 0; nt < 8; nt++) {
                int n = wn * 64 + nt * 8 + g;
                bf[nt][0] = sB[(kk + t4) * SB_ + n];
                bf[nt][1] = sB[(kk + t4 + 4) * SB_ + n];
            }
            #pragma unroll
            for (int mt = 0; mt < 2; mt++)
                #pragma unroll
                for (int nt = 0; nt < 8; nt++)
                    mma_tf32(acc[mt][nt][0], acc[mt][nt][1], acc[mt][nt][2], acc[mt][nt][3],
                             af[mt][0], af[mt][1], af[mt][2], af[mt][3],
                             bf[nt][0], bf[nt][1]);
        }
        __syncthreads();
    }

    // epilogue
    #pragma unroll
    for (int mt = 0; mt < 2; mt++) {
        #pragma unroll
        for (int nt = 0; nt < 8; nt++) {
            int row = m0 + wm * 32 + mt * 16 + g;
            int col = n0 + wn * 64 + nt * 8 + t4 * 2;
            if (MODE == 0) {
                *reinterpret_cast<float2*>(C + (size_t)row * NLD + col) =
                    make_float2(acc[mt][nt][0], acc[mt][nt][1]);
                *reinterpret_cast<float2*>(C + (size_t)(row + 8) * NLD + col) =
                    make_float2(acc[mt][nt][2], acc[mt][nt][3]);
            } else {
                #pragma unroll
                for (int half = 0; half < 2; half++) {
                    int m = row + half * 8;
                    int b = m >> 10, l = m & 1023;
                    int s = col >> 10, rem = col & 1023;
                    int h = rem >> 6, d = rem & 63;
                    float* dst = (s == 0) ? g_q : (s == 1) ? g_k : g_v;
                    *reinterpret_cast<float2*>(dst + (size_t)((b * H_ + h) * L_ + l) * D_ + d) =
                        make_float2(acc[mt][nt][half * 2], acc[mt][nt][half * 2 + 1]);
                }
            }
        }
    }
}

// ---------------- kernel 2: RoPE in place on q,k ----------------
__global__ void k_rope() {
    int t = blockIdx.x * 256 + threadIdx.x;     // B*H*L*32 threads
    int bh = t >> 15;
    int rem = t & 32767;
    int l = rem >> 5;
    int j = rem & 31;
    float invf = expf(-(float)j * (logf(10000.0f) / 32.0f));
    float ang = (float)l * invf;
    float cs = cosf(ang), sn = sinf(ang);
    int base = (bh << 16) + (l << 6) + j;
    float q1 = g_q[base], q2 = g_q[base + 32];
    g_q[base]      = q1 * cs - q2 * sn;
    g_q[base + 32] = q2 * cs + q1 * sn;
    float k1 = g_k[base], k2 = g_k[base + 32];
    g_k[base]      = k1 * cs - k2 * sn;
    g_k[base + 32] = k2 * cs + k1 * sn;
}

// ---------------- kernel 3: scores = q k^T * scale (lower-tri tiles only) ----------------
__global__ void k_scores() {
    int jt = blockIdx.x, it = blockIdx.y, bh = blockIdx.z;
    if (jt > it) return;
    __shared__ float Qs[64][65];
    __shared__ float Ks[64][65];
    int tx = threadIdx.x, ty = threadIdx.y;
    int tid = ty * 16 + tx;
    int i0 = it * 64, j0 = jt * 64;
    const float* qb = g_q + (bh * L_ + i0) * D_;
    const float* kb = g_k + (bh * L_ + j0) * D_;
    #pragma unroll
    for (int rr = 0; rr < 4; rr++) {
        int row = (tid >> 4) + rr * 16;
        int c4 = (tid & 15) * 4;
        float4 vq = *reinterpret_cast<const float4*>(qb + row * D_ + c4);
        Qs[row][c4] = vq.x; Qs[row][c4 + 1] = vq.y; Qs[row][c4 + 2] = vq.z; Qs[row][c4 + 3] = vq.w;
        float4 vk = *reinterpret_cast<const float4*>(kb + row * D_ + c4);
        Ks[row][c4] = vk.x; Ks[row][c4 + 1] = vk.y; Ks[row][c4 + 2] = vk.z; Ks[row][c4 + 3] = vk.w;
    }
    __syncthreads();
    float acc[4][4] = {};
    #pragma unroll
    for (int d = 0; d < 64; d++) {
        float a[4], b[4];
        #pragma unroll
        for (int r = 0; r < 4; r++) a[r] = Qs[ty + 16 * r][d];
        #pragma unroll
        for (int c = 0; c < 4; c++) b[c] = Ks[tx + 16 * c][d];
        #pragma unroll
        for (int r = 0; r < 4; r++)
            #pragma unroll
            for (int c = 0; c < 4; c++) acc[r][c] += a[r] * b[c];
    }
    bool diag = (it == jt);
    #pragma unroll
    for (int r = 0; r < 4; r++) {
        int i = i0 + ty + 16 * r;
        #pragma unroll
        for (int c = 0; c < 4; c++) {
            int j = j0 + tx + 16 * c;
            float v = acc[r][c] * 0.125f;
            if (diag && j > i) v = 0.0f;           // stays 0 through softmax; PV needs no mask
            g_s[(bh * L_ + i) * L_ + j] = v;
        }
    }
}

// ---------------- kernel 4: kerple bias + DAPE MLP, in place (j<=i only) ----------------
__global__ void k_dape(const float* __restrict__ log_p, const float* __restrict__ log_a,
                       const float* __restrict__ w1, const float* __restrict__ b1,
                       const float* __restrict__ w2, const float* __restrict__ b2) {
    __shared__ float w1s[1024];
    __shared__ float w2s[512];
    __shared__ float b1s[32], b2s[16], ps[16], as_[16];
    int tx = threadIdx.x;
    for (int t = tx; t < 1024; t += 256) w1s[t] = w1[t];
    for (int t = tx; t < 512; t += 256) w2s[t] = w2[t];
    if (tx < 32) b1s[tx] = b1[tx];
    if (tx < 16) {
        b2s[tx] = b2[tx];
        ps[tx]  = log1pf(expf(log_p[tx]));
        as_[tx] = log1pf(expf(log_a[tx]));
    }
    __syncthreads();

    int i = blockIdx.y;
    int bb = blockIdx.z;
    int j = blockIdx.x * 256 + tx;
    if (j > i) return;
    float dist = (float)(i - j);
    int off = bb * (H_ * L_ * L_) + i * L_ + j;

    float c[32];
    #pragma unroll
    for (int h = 0; h < 16; h++) c[h] = g_s[off + h * (L_ * L_)];
    #pragma unroll
    for (int h = 0; h < 16; h++) c[16 + h] = -ps[h] * log1pf(as_[h] * dist);

    float ref[16];
    #pragma unroll
    for (int h = 0; h < 16; h++) ref[h] = b2s[h];

    #pragma unroll 4
    for (int u = 0; u < 32; u++) {
        float acc = b1s[u];
        #pragma unroll
        for (int kk = 0; kk < 32; kk++) acc += c[kk] * w1s[kk * 32 + u];
        float g = 0.5f * acc * (1.0f + erff(acc * 0.70710678118f));
        #pragma unroll
        for (int h = 0; h < 16; h++) ref[h] += g * w2s[u * 16 + h];
    }
    #pragma unroll
    for (int h = 0; h < 16; h++)
        g_s[off + h * (L_ * L_)] = c[h] + c[16 + h] + ref[h];
}

// ---------------- kernel 5: causal softmax per row ----------------
__global__ void k_softmax() {
    int row = blockIdx.x;           // bh*L + i
    int i = row & 1023;
    int n = i + 1;
    float* S = g_s + (size_t)row * L_;
    __shared__ float buf[1024];
    __shared__ float redm[4], reds[4];
    int tx = threadIdx.x;

    float m = -1e30f;
    for (int j = tx; j < n; j += 128) { float v = S[j]; buf[j] = v; m = fmaxf(m, v); }
    #pragma unroll
    for (int o = 16; o; o >>= 1) m = fmaxf(m, __shfl_xor_sync(0xffffffffu, m, o));
    if ((tx & 31) == 0) redm[tx >> 5] = m;
    __syncthreads();
    m = fmaxf(fmaxf(redm[0], redm[1]), fmaxf(redm[2], redm[3]));

    float sum = 0.0f;
    for (int j = tx; j < n; j += 128) { float e = expf(buf[j] - m); buf[j] = e; sum += e; }
    #pragma unroll
    for (int o = 16; o; o >>= 1) sum += __shfl_xor_sync(0xffffffffu, sum, o);
    if ((tx & 31) == 0) reds[tx >> 5] = sum;
    __syncthreads();
    sum = reds[0] + reds[1] + reds[2] + reds[3];
    float inv = 1.0f / sum;
    for (int j = tx; j < n; j += 128) S[j] = buf[j] * inv;
}

// ---------------- kernel 6: out = weights @ v (lower-tri j loop) ----------------
__global__ void k_pv() {
    int it = blockIdx.x, bh = blockIdx.y;
    int tx = threadIdx.x, ty = threadIdx.y;
    int tid = ty * 16 + tx;
    int i0 = it * 64;
    __shared__ float Ws[64][65];
    __shared__ float Vs[64][65];
    float acc[4][4] = {};

    for (int jt = 0; jt <= it; jt++) {
        int j0 = jt * 64;
        const float* wb = g_s + (size_t)(bh * L_ + i0) * L_ + j0;
        const float* vb = g_v + (bh * L_ + j0) * D_;
        #pragma unroll
        for (int rr = 0; rr < 4; rr++) {
            int row = (tid >> 4) + rr * 16;
            int c4 = (tid & 15) * 4;
            float4 vw = *reinterpret_cast<const float4*>(wb + (size_t)row * L_ + c4);
            Ws[row][c4] = vw.x; Ws[row][c4 + 1] = vw.y; Ws[row][c4 + 2] = vw.z; Ws[row][c4 + 3] = vw.w;
            float4 vv = *reinterpret_cast<const float4*>(vb + row * D_ + c4);
            Vs[row][c4] = vv.x; Vs[row][c4 + 1] = vv.y; Vs[row][c4 + 2] = vv.z; Vs[row][c4 + 3] = vv.w;
        }
        __syncthreads();
        #pragma unroll
        for (int jj = 0; jj < 64; jj++) {
            float a[4], b[4];
            #pragma unroll
            for (int r = 0; r < 4; r++) a[r] = Ws[ty + 16 * r][jj];
            #pragma unroll
            for (int c = 0; c < 4; c++) b[c] = Vs[jj][tx + 16 * c];
            #pragma unroll
            for (int r = 0; r < 4; r++)
                #pragma unroll
                for (int c = 0; c < 4; c++) acc[r][c] += a[r] * b[c];
        }
        __syncthreads();
    }
    int b = bh >> 4, h = bh & 15;
    #pragma unroll
    for (int r = 0; r < 4; r++) {
        int i = i0 + ty + 16 * r;
        #pragma unroll
        for (int c = 0; c < 4; c++) {
            int d = tx + 16 * c;
            g_o[(b * L_ + i) * HD_ + h * D_ + d] = acc[r][c];
        }
    }
}

// ---------------- launch ----------------
extern "C" void kernel_launch(void* const* d_in, const int* in_sizes, int n_in,
                              void* d_out, int out_size) {
    const float* x     = (const float*)d_in[0];
    const float* w_qkv = (const float*)d_in[1];
    const float* w_o   = (const float*)d_in[2];
    const float* log_p = (const float*)d_in[3];
    const float* log_a = (const float*)d_in[4];
    const float* w1    = (const float*)d_in[5];
    const float* b1    = (const float*)d_in[6];
    const float* w2    = (const float*)d_in[7];
    const float* b2    = (const float*)d_in[8];
    float* y = (float*)d_out;

    dim3 blk16(16, 16);

    void* o_ptr = nullptr;
    cudaGetSymbolAddress(&o_ptr, g_o);

    // 1. QKV projection (tf32 mma): qkv scatter epilogue
    k_gemm_mma<N3_, 1><<<dim3(N3_ / 128, M_ / 128), 256>>>(x, w_qkv, nullptr);
    // 2. RoPE
    k_rope<<<(B_ * H_ * L_ * 32) / 256, 256>>>();
    // 3. scores (lower-tri tiles)
    k_scores<<<dim3(16, 16, B_ * H_), blk16>>>();
    // 4. kerple + DAPE MLP
    k_dape<<<dim3(4, L_, B_), 256>>>(log_p, log_a, w1, b1, w2, b2);
    // 5. causal softmax
    k_softmax<<<B_ * H_ * L_, 128>>>();
    // 6. PV
    k_pv<<<dim3(16, B_ * H_), blk16>>>();
    // 7. output projection (tf32 mma)
    k_gemm_mma<HID_, 0><<<dim3(HID_ / 128, M_ / 128), 256>>>((const float*)o_ptr, w_o, y);
}

// round 5
// speedup vs baseline: 2.5467x; 1.4655x over previous
#include <cuda_runtime.h>
#include <math.h>

#define B_  2
#define L_  1024
#define H_  16
#define D_  64
#define HID_ 1024
#define N3_ 3072
#define HD_ 1024   // H*D
#define M_  2048   // B*L

// ---------------- scratch (device globals; no allocations) ----------------
__device__ float g_q[B_ * H_ * L_ * D_];   // (B,H,L,D)
__device__ float g_k[B_ * H_ * L_ * D_];
__device__ float g_v[B_ * H_ * L_ * D_];
__device__ float g_s[B_ * H_ * L_ * L_];   // scores / weights, 128 MB
__device__ float g_o[B_ * L_ * HD_];       // attention output (B,L,H*D)

// ---------------- tf32 helpers ----------------
__device__ __forceinline__ unsigned f2tf(float x) {
    unsigned r;
    asm("cvt.rna.tf32.f32 %0, %1;" : "=r"(r) : "f"(x));
    return r;
}

__device__ __forceinline__ void mma_tf32(float& d0, float& d1, float& d2, float& d3,
                                         unsigned a0, unsigned a1, unsigned a2, unsigned a3,
                                         unsigned b0, unsigned b1) {
    asm volatile(
        "mma.sync.aligned.m16n8k8.row.col.f32.tf32.tf32.f32 "
        "{%0,%1,%2,%3}, {%4,%5,%6,%7}, {%8,%9}, {%0,%1,%2,%3};"
        : "+f"(d0), "+f"(d1), "+f"(d2), "+f"(d3)
        : "r"(a0), "r"(a1), "r"(a2), "r"(a3), "r"(b0), "r"(b1));
}

// ---------------- generic tf32 mma GEMM: C(M x N) = A(M x 1024) @ B(1024 x N) ----------------
#define SA_ 36
#define SB_ 136

template<int NLD, int MODE>
__global__ void __launch_bounds__(256)
k_gemm_mma(const float* __restrict__ A, const float* __restrict__ Bm, float* __restrict__ C) {
    __shared__ unsigned sA[128 * SA_];
    __shared__ unsigned sB[32 * SB_];

    int tid = threadIdx.x;
    int lane = tid & 31, wid = tid >> 5;
    int g = lane >> 2, t4 = lane & 3;
    int wm = wid & 3, wn = wid >> 2;
    int m0 = blockIdx.y * 128, n0 = blockIdx.x * 128;

    float acc[2][8][4];
    #pragma unroll
    for (int mt = 0; mt < 2; mt++)
        #pragma unroll
        for (int nt = 0; nt < 8; nt++)
            #pragma unroll
            for (int c = 0; c < 4; c++) acc[mt][nt][c] = 0.0f;

    for (int k0 = 0; k0 < HID_; k0 += 32) {
        #pragma unroll
        for (int it = 0; it < 4; it++) {
            int row = it * 32 + (tid >> 3);
            int col = (tid & 7) * 4;
            float4 v = *reinterpret_cast<const float4*>(A + (size_t)(m0 + row) * HID_ + k0 + col);
            sA[row * SA_ + col + 0] = f2tf(v.x);
            sA[row * SA_ + col + 1] = f2tf(v.y);
            sA[row * SA_ + col + 2] = f2tf(v.z);
            sA[row * SA_ + col + 3] = f2tf(v.w);
        }
        #pragma unroll
        for (int it = 0; it < 4; it++) {
            int row = it * 8 + (tid >> 5);
            int col = (tid & 31) * 4;
            float4 v = *reinterpret_cast<const float4*>(Bm + (size_t)(k0 + row) * NLD + n0 + col);
            sB[row * SB_ + col + 0] = f2tf(v.x);
            sB[row * SB_ + col + 1] = f2tf(v.y);
            sB[row * SB_ + col + 2] = f2tf(v.z);
            sB[row * SB_ + col + 3] = f2tf(v.w);
        }
        __syncthreads();

        #pragma unroll
        for (int ks = 0; ks < 4; ks++) {
            int kk = ks * 8;
            unsigned af[2][4];
            #pragma unroll
            for (int mt = 0; mt < 2; mt++) {
                int r = wm * 32 + mt * 16 + g;
                af[mt][0] = sA[r * SA_ + kk + t4];
                af[mt][1] = sA[(r + 8) * SA_ + kk + t4];
                af[mt][2] = sA[r * SA_ + kk + t4 + 4];
                af[mt][3] = sA[(r + 8) * SA_ + kk + t4 + 4];
            }
            unsigned bf[8][2];
            #pragma unroll
            for (int nt = 0; nt < 8; nt++) {
                int n = wn * 64 + nt * 8 + g;
                bf[nt][0] = sB[(kk + t4) * SB_ + n];
                bf[nt][1] = sB[(kk + t4 + 4) * SB_ + n];
            }
            #pragma unroll
            for (int mt = 0; mt < 2; mt++)
                #pragma unroll
                for (int nt = 0; nt < 8; nt++)
                    mma_tf32(acc[mt][nt][0], acc[mt][nt][1], acc[mt][nt][2], acc[mt][nt][3],
                             af[mt][0], af[mt][1], af[mt][2], af[mt][3],
                             bf[nt][0], bf[nt][1]);
        }
        __syncthreads();
    }

    #pragma unroll
    for (int mt = 0; mt < 2; mt++) {
        #pragma unroll
        for (int nt = 0; nt < 8; nt++) {
            int row = m0 + wm * 32 + mt * 16 + g;
            int col = n0 + wn * 64 + nt * 8 + t4 * 2;
            if (MODE == 0) {
                *reinterpret_cast<float2*>(C + (size_t)row * NLD + col) =
                    make_float2(acc[mt][nt][0], acc[mt][nt][1]);
                *reinterpret_cast<float2*>(C + (size_t)(row + 8) * NLD + col) =
                    make_float2(acc[mt][nt][2], acc[mt][nt][3]);
            } else {
                #pragma unroll
                for (int half = 0; half < 2; half++) {
                    int m = row + half * 8;
                    int b = m >> 10, l = m & 1023;
                    int s = col >> 10, rem = col & 1023;
                    int h = rem >> 6, d = rem & 63;
                    float* dst = (s == 0) ? g_q : (s == 1) ? g_k : g_v;
                    *reinterpret_cast<float2*>(dst + (size_t)((b * H_ + h) * L_ + l) * D_ + d) =
                        make_float2(acc[mt][nt][half * 2], acc[mt][nt][half * 2 + 1]);
                }
            }
        }
    }
}

// ---------------- kernel 2: RoPE in place on q,k ----------------
__global__ void k_rope() {
    int t = blockIdx.x * 256 + threadIdx.x;
    int bh = t >> 15;
    int rem = t & 32767;
    int l = rem >> 5;
    int j = rem & 31;
    float invf = expf(-(float)j * (logf(10000.0f) / 32.0f));
    float ang = (float)l * invf;
    float cs = cosf(ang), sn = sinf(ang);
    int base = (bh << 16) + (l << 6) + j;
    float q1 = g_q[base], q2 = g_q[base + 32];
    g_q[base]      = q1 * cs - q2 * sn;
    g_q[base + 32] = q2 * cs + q1 * sn;
    float k1 = g_k[base], k2 = g_k[base + 32];
    g_k[base]      = k1 * cs - k2 * sn;
    g_k[base + 32] = k2 * cs + k1 * sn;
}

// ---------------- kernel 3: scores = q k^T * scale (tf32 mma, 128x64 tiles, D chunked) ----------------
__global__ void __launch_bounds__(256) k_scores_mma() {
    int jt = blockIdx.x, it = blockIdx.y, bh = blockIdx.z;
    int i0 = it * 128, j0 = jt * 64;
    if (j0 > i0 + 127) return;
    __shared__ unsigned sQ[128 * 36];    // 128 rows x 32 d-chunk
    __shared__ unsigned sKt[32 * 72];    // [d][j] chunk

    int tid = threadIdx.x;
    int lane = tid & 31, wid = tid >> 5;
    int g = lane >> 2, t4 = lane & 3;
    int wm = wid & 3, wn = wid >> 2;

    const float* qb = g_q + (size_t)(bh * L_ + i0) * D_;
    const float* kb = g_k + (size_t)(bh * L_ + j0) * D_;

    float acc[2][4][4];
    #pragma unroll
    for (int mt = 0; mt < 2; mt++)
        #pragma unroll
        for (int nt = 0; nt < 4; nt++)
            #pragma unroll
            for (int c = 0; c < 4; c++) acc[mt][nt][c] = 0.0f;

    #pragma unroll
    for (int kc = 0; kc < 64; kc += 32) {
        #pragma unroll
        for (int u = 0; u < 4; u++) {      // Q chunk: 128x32
            int id = u * 256 + tid;
            int row = id >> 3, c4 = (id & 7) * 4;
            float4 v = *reinterpret_cast<const float4*>(qb + row * D_ + kc + c4);
            sQ[row * 36 + c4 + 0] = f2tf(v.x);
            sQ[row * 36 + c4 + 1] = f2tf(v.y);
            sQ[row * 36 + c4 + 2] = f2tf(v.z);
            sQ[row * 36 + c4 + 3] = f2tf(v.w);
        }
        #pragma unroll
        for (int u = 0; u < 2; u++) {      // K chunk: 64x32, transposed to [d][j]
            int id = u * 256 + tid;
            int jr = id >> 3, c4 = (id & 7) * 4;
            float4 v = *reinterpret_cast<const float4*>(kb + jr * D_ + kc + c4);
            sKt[(c4 + 0) * 72 + jr] = f2tf(v.x);
            sKt[(c4 + 1) * 72 + jr] = f2tf(v.y);
            sKt[(c4 + 2) * 72 + jr] = f2tf(v.z);
            sKt[(c4 + 3) * 72 + jr] = f2tf(v.w);
        }
        __syncthreads();

        #pragma unroll
        for (int ks = 0; ks < 4; ks++) {
            int kk = ks * 8;
            unsigned af[2][4];
            #pragma unroll
            for (int mt = 0; mt < 2; mt++) {
                int r = wm * 32 + mt * 16 + g;
                af[mt][0] = sQ[r * 36 + kk + t4];
                af[mt][1] = sQ[(r + 8) * 36 + kk + t4];
                af[mt][2] = sQ[r * 36 + kk + t4 + 4];
                af[mt][3] = sQ[(r + 8) * 36 + kk + t4 + 4];
            }
            #pragma unroll
            for (int nt = 0; nt < 4; nt++) {
                int n = wn * 32 + nt * 8 + g;
                unsigned b0 = sKt[(kk + t4) * 72 + n];
                unsigned b1 = sKt[(kk + t4 + 4) * 72 + n];
                #pragma unroll
                for (int mt = 0; mt < 2; mt++)
                    mma_tf32(acc[mt][nt][0], acc[mt][nt][1], acc[mt][nt][2], acc[mt][nt][3],
                             af[mt][0], af[mt][1], af[mt][2], af[mt][3], b0, b1);
            }
        }
        __syncthreads();
    }

    bool edge = (j0 + 63 > i0);
    #pragma unroll
    for (int mt = 0; mt < 2; mt++) {
        #pragma unroll
        for (int nt = 0; nt < 4; nt++) {
            #pragma unroll
            for (int half = 0; half < 2; half++) {
                int i = i0 + wm * 32 + mt * 16 + g + half * 8;
                int j = j0 + wn * 32 + nt * 8 + t4 * 2;
                float v0 = acc[mt][nt][half * 2] * 0.125f;
                float v1 = acc[mt][nt][half * 2 + 1] * 0.125f;
                if (edge) {
                    if (j > i) v0 = 0.0f;
                    if (j + 1 > i) v1 = 0.0f;
                }
                *reinterpret_cast<float2*>(g_s + (size_t)(bh * L_ + i) * L_ + j) =
                    make_float2(v0, v1);
            }
        }
    }
}

// ---------------- kernel 4: kerple + DAPE MLP (tf32 mma), in place ----------------
__global__ void __launch_bounds__(256)
k_dape_mma(const float* __restrict__ log_p, const float* __restrict__ log_a,
           const float* __restrict__ w1, const float* __restrict__ b1,
           const float* __restrict__ w2, const float* __restrict__ b2) {
    int jt = blockIdx.x;
    int i = blockIdx.y;
    int b = blockIdx.z;
    int j0 = jt * 128;
    if (j0 > i) return;

    __shared__ float sC[128 * 36];       // combined: cols 0..15 scores, 16..31 kerple
    __shared__ float sH[128 * 36];       // hidden after gelu
    __shared__ unsigned w1s[32 * 40];    // [k][n] tf32
    __shared__ unsigned w2s[32 * 24];
    __shared__ float b1s[32], b2s[16], ps[16], as_[16];

    int tid = threadIdx.x;
    for (int t = tid; t < 1024; t += 256) w1s[(t >> 5) * 40 + (t & 31)] = f2tf(w1[t]);
    for (int t = tid; t < 512; t += 256)  w2s[(t >> 4) * 24 + (t & 15)] = f2tf(w2[t]);
    if (tid < 32) b1s[tid] = b1[tid];
    if (tid < 16) {
        b2s[tid] = b2[tid];
        ps[tid]  = log1pf(expf(log_p[tid]));
        as_[tid] = log1pf(expf(log_a[tid]));
    }
    __syncthreads();

    size_t off = (size_t)b * (H_ * L_ * L_) + (size_t)i * L_ + j0;
    if (tid < 128) {
        int r = tid;
        #pragma unroll
        for (int h = 0; h < 16; h++)
            sC[r * 36 + h] = g_s[off + (size_t)h * (L_ * L_) + r];
    } else {
        int r = tid - 128;
        float dist = fabsf((float)(i - (j0 + r)));
        #pragma unroll
        for (int h = 0; h < 16; h++)
            sC[r * 36 + 16 + h] = -ps[h] * log1pf(as_[h] * dist);
    }
    __syncthreads();

    int lane = tid & 31, wid = tid >> 5;
    int g = lane >> 2, t4 = lane & 3;
    int r0 = wid * 16;

    // layer 1: [16x32] rows @ w1[32x32]
    float acc1[4][4];
    #pragma unroll
    for (int nt = 0; nt < 4; nt++)
        #pragma unroll
        for (int c = 0; c < 4; c++) acc1[nt][c] = 0.0f;
    #pragma unroll
    for (int ks = 0; ks < 4; ks++) {
        int kk = ks * 8;
        unsigned a0 = f2tf(sC[(r0 + g) * 36 + kk + t4]);
        unsigned a1 = f2tf(sC[(r0 + 8 + g) * 36 + kk + t4]);
        unsigned a2 = f2tf(sC[(r0 + g) * 36 + kk + t4 + 4]);
        unsigned a3 = f2tf(sC[(r0 + 8 + g) * 36 + kk + t4 + 4]);
        #pragma unroll
        for (int nt = 0; nt < 4; nt++) {
            unsigned b0 = w1s[(kk + t4) * 40 + nt * 8 + g];
            unsigned b1f = w1s[(kk + t4 + 4) * 40 + nt * 8 + g];
            mma_tf32(acc1[nt][0], acc1[nt][1], acc1[nt][2], acc1[nt][3],
                     a0, a1, a2, a3, b0, b1f);
        }
    }
    // gelu epilogue -> sH
    #pragma unroll
    for (int nt = 0; nt < 4; nt++)
        #pragma unroll
        for (int half = 0; half < 2; half++)
            #pragma unroll
            for (int q = 0; q < 2; q++) {
                int col = nt * 8 + t4 * 2 + q;
                int row = r0 + g + half * 8;
                float x = acc1[nt][half * 2 + q] + b1s[col];
                sH[row * 36 + col] = 0.5f * x * (1.0f + erff(x * 0.70710678118f));
            }
    __syncthreads();

    // layer 2: [16x32] @ w2[32x16]
    float acc2[2][4];
    #pragma unroll
    for (int nt = 0; nt < 2; nt++)
        #pragma unroll
        for (int c = 0; c < 4; c++) acc2[nt][c] = 0.0f;
    #pragma unroll
    for (int ks = 0; ks < 4; ks++) {
        int kk = ks * 8;
        unsigned a0 = f2tf(sH[(r0 + g) * 36 + kk + t4]);
        unsigned a1 = f2tf(sH[(r0 + 8 + g) * 36 + kk + t4]);
        unsigned a2 = f2tf(sH[(r0 + g) * 36 + kk + t4 + 4]);
        unsigned a3 = f2tf(sH[(r0 + 8 + g) * 36 + kk + t4 + 4]);
        #pragma unroll
        for (int nt = 0; nt < 2; nt++) {
            unsigned b0 = w2s[(kk + t4) * 24 + nt * 8 + g];
            unsigned b1f = w2s[(kk + t4 + 4) * 24 + nt * 8 + g];
            mma_tf32(acc2[nt][0], acc2[nt][1], acc2[nt][2], acc2[nt][3],
                     a0, a1, a2, a3, b0, b1f);
        }
    }
    // store: score + kerple + refined, predicated j<=i
    #pragma unroll
    for (int nt = 0; nt < 2; nt++)
        #pragma unroll
        for (int half = 0; half < 2; half++) {
            int row = r0 + g + half * 8;
            int j = j0 + row;
            if (j <= i) {
                #pragma unroll
                for (int q = 0; q < 2; q++) {
                    int h = nt * 8 + t4 * 2 + q;
                    float outv = sC[row * 36 + h] + sC[row * 36 + 16 + h]
                               + acc2[nt][half * 2 + q] + b2s[h];
                    g_s[off + (size_t)h * (L_ * L_) + row] = outv;
                }
            }
        }
}

// ---------------- kernel 5: causal softmax per row ----------------
__global__ void k_softmax() {
    int row = blockIdx.x;
    int i = row & 1023;
    int n = i + 1;
    float* S = g_s + (size_t)row * L_;
    __shared__ float buf[1024];
    __shared__ float redm[4], reds[4];
    int tx = threadIdx.x;

    float m = -1e30f;
    for (int j = tx; j < n; j += 128) { float v = S[j]; buf[j] = v; m = fmaxf(m, v); }
    #pragma unroll
    for (int o = 16; o; o >>= 1) m = fmaxf(m, __shfl_xor_sync(0xffffffffu, m, o));
    if ((tx & 31) == 0) redm[tx >> 5] = m;
    __syncthreads();
    m = fmaxf(fmaxf(redm[0], redm[1]), fmaxf(redm[2], redm[3]));

    float sum = 0.0f;
    for (int j = tx; j < n; j += 128) { float e = expf(buf[j] - m); buf[j] = e; sum += e; }
    #pragma unroll
    for (int o = 16; o; o >>= 1) sum += __shfl_xor_sync(0xffffffffu, sum, o);
    if ((tx & 31) == 0) reds[tx >> 5] = sum;
    __syncthreads();
    sum = reds[0] + reds[1] + reds[2] + reds[3];
    float inv = 1.0f / sum;
    for (int j = tx; j < n; j += 128) S[j] = buf[j] * inv;
}

// ---------------- kernel 6: out = weights @ v (tf32 mma, K-chunks of 32) ----------------
__global__ void __launch_bounds__(256) k_pv_mma() {
    int it = blockIdx.x, bh = blockIdx.y;
    __shared__ unsigned sW[128 * 36];
    __shared__ unsigned sV[32 * 72];
    int i0 = it * 128;
    int tid = threadIdx.x;
    int lane = tid & 31, wid = tid >> 5;
    int g = lane >> 2, t4 = lane & 3;
    int wm = wid & 3, wn = wid >> 2;

    float acc[2][4][4];
    #pragma unroll
    for (int mt = 0; mt < 2; mt++)
        #pragma unroll
        for (int nt = 0; nt < 4; nt++)
            #pragma unroll
            for (int c = 0; c < 4; c++) acc[mt][nt][c] = 0.0f;

    const float* wbase = g_s + (size_t)(bh * L_ + i0) * L_;
    const float* vbase = g_v + (size_t)bh * L_ * D_;
    int nch = (it + 1) * 4;

    for (int ch = 0; ch < nch; ch++) {
        int j0 = ch * 32;
        #pragma unroll
        for (int u = 0; u < 4; u++) {      // W: 128x32
            int id = u * 256 + tid;
            int row = id >> 3, c4 = (id & 7) * 4;
            float4 v = *reinterpret_cast<const float4*>(wbase + (size_t)row * L_ + j0 + c4);
            sW[row * 36 + c4 + 0] = f2tf(v.x);
            sW[row * 36 + c4 + 1] = f2tf(v.y);
            sW[row * 36 + c4 + 2] = f2tf(v.z);
            sW[row * 36 + c4 + 3] = f2tf(v.w);
        }
        #pragma unroll
        for (int u = 0; u < 2; u++) {      // V: 32x64
            int id = u * 256 + tid;
            int row = id >> 4, c4 = (id & 15) * 4;
            float4 v = *reinterpret_cast<const float4*>(vbase + (size_t)(j0 + row) * D_ + c4);
            sV[row * 72 + c4 + 0] = f2tf(v.x);
            sV[row * 72 + c4 + 1] = f2tf(v.y);
            sV[row * 72 + c4 + 2] = f2tf(v.z);
            sV[row * 72 + c4 + 3] = f2tf(v.w);
        }
        __syncthreads();

        #pragma unroll
        for (int ks = 0; ks < 4; ks++) {
            int kk = ks * 8;
            unsigned af[2][4];
            #pragma unroll
            for (int mt = 0; mt < 2; mt++) {
                int r = wm * 32 + mt * 16 + g;
                af[mt][0] = sW[r * 36 + kk + t4];
                af[mt][1] = sW[(r + 8) * 36 + kk + t4];
                af[mt][2] = sW[r * 36 + kk + t4 + 4];
                af[mt][3] = sW[(r + 8) * 36 + kk + t4 + 4];
            }
            #pragma unroll
            for (int nt = 0; nt < 4; nt++) {
                int n = wn * 32 + nt * 8 + g;
                unsigned b0 = sV[(kk + t4) * 72 + n];
                unsigned b1 = sV[(kk + t4 + 4) * 72 + n];
                #pragma unroll
                for (int mt = 0; mt < 2; mt++)
                    mma_tf32(acc[mt][nt][0], acc[mt][nt][1], acc[mt][nt][2], acc[mt][nt][3],
                             af[mt][0], af[mt][1], af[mt][2], af[mt][3], b0, b1);
            }
        }
        __syncthreads();
    }

    int b = bh >> 4, h = bh & 15;
    #pragma unroll
    for (int mt = 0; mt < 2; mt++)
        #pragma unroll
        for (int nt = 0; nt < 4; nt++)
            #pragma unroll
            for (int half = 0; half < 2; half++) {
                int i = i0 + wm * 32 + mt * 16 + g + half * 8;
                int d = wn * 32 + nt * 8 + t4 * 2;
                *reinterpret_cast<float2*>(g_o + (size_t)(b * L_ + i) * HD_ + h * D_ + d) =
                    make_float2(acc[mt][nt][half * 2], acc[mt][nt][half * 2 + 1]);
            }
}

// ---------------- launch ----------------
extern "C" void kernel_launch(void* const* d_in, const int* in_sizes, int n_in,
                              void* d_out, int out_size) {
    const float* x     = (const float*)d_in[0];
    const float* w_qkv = (const float*)d_in[1];
    const float* w_o   = (const float*)d_in[2];
    const float* log_p = (const float*)d_in[3];
    const float* log_a = (const float*)d_in[4];
    const float* w1    = (const float*)d_in[5];
    const float* b1    = (const float*)d_in[6];
    const float* w2    = (const float*)d_in[7];
    const float* b2    = (const float*)d_in[8];
    float* y = (float*)d_out;

    void* o_ptr = nullptr;
    cudaGetSymbolAddress(&o_ptr, g_o);

    // 1. QKV projection (tf32 mma) with q/k/v scatter
    k_gemm_mma<N3_, 1><<<dim3(N3_ / 128, M_ / 128), 256>>>(x, w_qkv, nullptr);
    // 2. RoPE
    k_rope<<<(B_ * H_ * L_ * 32) / 256, 256>>>();
    // 3. scores (tf32 mma, lower-tri tiles)
    k_scores_mma<<<dim3(16, 8, B_ * H_), 256>>>();
    // 4. kerple + DAPE MLP (tf32 mma)
    k_dape_mma<<<dim3(8, L_, B_), 256>>>(log_p, log_a, w1, b1, w2, b2);
    // 5. causal softmax
    k_softmax<<<B_ * H_ * L_, 128>>>();
    // 6. PV (tf32 mma)
    k_pv_mma<<<dim3(8, B_ * H_), 256>>>();
    // 7. output projection (tf32 mma)
    k_gemm_mma<HID_, 0><<<dim3(HID_ / 128, M_ / 128), 256>>>((const float*)o_ptr, w_o, y);
}